// round 16
// baseline (speedup 1.0000x reference)
#include <cuda_runtime.h>
#include <cuda_bf16.h>
#include <math.h>
#include <stdint.h>

#define NN 20000
#define MPAD 20096          // 314 * 64
#define NE 320000
#define NB 64
#define HID 128
#define DEPTH 4
#define NFREQ 8
#define KFK (NFREQ * HID)   // 1024
#define TWO_PI_F 6.283185307179586f
#define TILE_BLOCKS 313

typedef __nv_bfloat16 bf16;

// ==================== scratch (static device allocations) ====================
__device__ float g_h[MPAD * HID];
__device__ float g_p12[2 * NN * HID];             // p1 | p2
__device__ bf16 g_Wfk_hi[DEPTH * HID * KFK];      // [l][n][k = i*8+f]
__device__ bf16 g_Wfk_lo[DEPTH * HID * KFK];
__device__ bf16 g_Wlin_hi[DEPTH * 2 * HID * HID]; // [l][part][n][k]
__device__ bf16 g_Wlin_lo[DEPTH * 2 * HID * HID];
__device__ float g_q1[NN];
__device__ float g_q2[NN];
__device__ float g_logits[NN];
__device__ float g_stats[2 * HID];                // [0:128) sum, [128:256) sumsq
__device__ float g_pooled[NB * HID];
__device__ unsigned g_umax;
__device__ float g_sumexp;
// CSR (built once per launch)
__device__ int g_count[NN];
__device__ int g_rowstart[NN + 1];
__device__ int g_perm[NE];
__device__ int g_esrc[NE];
__device__ float4 g_eax[NE];

// ==================== mma.sync / cp.async helpers ====================
__device__ __forceinline__ uint32_t smem_to_u32(const void* p) {
    uint32_t a;
    asm("{ .reg .u64 t; cvta.to.shared.u64 t, %1; cvt.u32.u64 %0, t; }" : "=r"(a) : "l"(p));
    return a;
}

#define LDSM4(r, addr) \
    asm volatile("ldmatrix.sync.aligned.m8n8.x4.shared.b16 {%0,%1,%2,%3}, [%4];" \
        : "=r"((r)[0]), "=r"((r)[1]), "=r"((r)[2]), "=r"((r)[3]) : "r"(addr))

#define MMA_BF16(c, a, b0, b1) \
    asm volatile("mma.sync.aligned.m16n8k16.row.col.f32.bf16.bf16.f32 " \
        "{%0,%1,%2,%3}, {%4,%5,%6,%7}, {%8,%9}, {%0,%1,%2,%3};" \
        : "+f"((c)[0]), "+f"((c)[1]), "+f"((c)[2]), "+f"((c)[3]) \
        : "r"((a)[0]), "r"((a)[1]), "r"((a)[2]), "r"((a)[3]), "r"(b0), "r"(b1))

__device__ __forceinline__ void cp16(uint32_t dst, const void* src) {
    asm volatile("cp.async.cg.shared.global [%0], [%1], 16;" :: "r"(dst), "l"(src));
}
#define CP_COMMIT() asm volatile("cp.async.commit_group;" ::: "memory")
#define CP_WAIT(n)  asm volatile("cp.async.wait_group %0;" :: "n"(n) : "memory")

#define BKP 72
#define A_MAT_B (64 * BKP * 2)                  // 9216
#define B_MAT_B (128 * BKP * 2)                 // 18432
#define STAGE_BYTES (2 * A_MAT_B + 2 * B_MAT_B) // 55296
#define GEMM_SMEM (2 * STAGE_BYTES)             // 110592

// pack 2 floats -> bf16 hi pair + lo pair
__device__ __forceinline__ void split2(float a, float b, uint32_t& hp, uint32_t& lp) {
    bf16 h0 = __float2bfloat16(a);
    bf16 h1 = __float2bfloat16(b);
    bf16 l0 = __float2bfloat16(a - __bfloat162float(h0));
    bf16 l1 = __float2bfloat16(b - __bfloat162float(h1));
    hp = (uint32_t)__bfloat16_as_ushort(h0) | ((uint32_t)__bfloat16_as_ushort(h1) << 16);
    lp = (uint32_t)__bfloat16_as_ushort(l0) | ((uint32_t)__bfloat16_as_ushort(l1) << 16);
}

// ==================== shared MMA core ====================
struct AccT { float a[2][4][4]; };

__device__ __forceinline__ void mma_chunk(uint32_t sb, int lane, int warp_m, int warp_n,
                                          AccT& acc) {
    uint32_t uAhi = sb;
    uint32_t uAlo = sb + A_MAT_B;
    uint32_t uBhi = sb + 2 * A_MAT_B;
    uint32_t uBlo = sb + 2 * A_MAT_B + B_MAT_B;
#pragma unroll
    for (int ks = 0; ks < 4; ++ks) {
        uint32_t ahi[2][4], alo[2][4];
#pragma unroll
        for (int mt = 0; mt < 2; ++mt) {
            int r = warp_m * 32 + mt * 16 + (lane & 15);
            int cc = ks * 16 + ((lane >> 4) << 3);
            uint32_t off = (uint32_t)(r * BKP + cc) * 2;
            LDSM4(ahi[mt], uAhi + off);
            LDSM4(alo[mt], uAlo + off);
        }
#pragma unroll
        for (int np = 0; np < 2; ++np) {
            int j = lane >> 3;
            int rn = warp_n * 32 + np * 16 + ((j >> 1) << 3) + (lane & 7);
            int cn = ks * 16 + ((j & 1) << 3);
            uint32_t off = (uint32_t)(rn * BKP + cn) * 2;
            uint32_t bhi[4], blo[4];
            LDSM4(bhi, uBhi + off);
            LDSM4(blo, uBlo + off);
#pragma unroll
            for (int mt = 0; mt < 2; ++mt) {
                MMA_BF16(acc.a[mt][2 * np],     ahi[mt], bhi[0], bhi[1]);
                MMA_BF16(acc.a[mt][2 * np],     alo[mt], bhi[0], bhi[1]);
                MMA_BF16(acc.a[mt][2 * np],     ahi[mt], blo[0], blo[1]);
                MMA_BF16(acc.a[mt][2 * np + 1], ahi[mt], bhi[2], bhi[3]);
                MMA_BF16(acc.a[mt][2 * np + 1], alo[mt], bhi[2], bhi[3]);
                MMA_BF16(acc.a[mt][2 * np + 1], ahi[mt], blo[2], blo[3]);
            }
        }
    }
}

__device__ __forceinline__ void epilogue(const AccT& acc, int m0, int lane,
                                         int warp_m, int warp_n,
                                         const float* bias, const float* add,
                                         float* out, int M) {
#pragma unroll
    for (int mt = 0; mt < 2; ++mt) {
        int r0 = m0 + warp_m * 32 + mt * 16 + (lane >> 2);
        int r1 = r0 + 8;
#pragma unroll
        for (int nt = 0; nt < 4; ++nt) {
            int c = warp_n * 32 + nt * 8 + 2 * (lane & 3);
            float bx = 0.f, by = 0.f;
            if (bias) { float2 bv = *(const float2*)&bias[c]; bx = bv.x; by = bv.y; }
            if (r0 < M) {
                float vx = acc.a[mt][nt][0] + bx, vy = acc.a[mt][nt][1] + by;
                if (add) {
                    float2 av = *(const float2*)&add[(size_t)r0 * HID + c];
                    vx += av.x; vy += av.y;
                }
                float2 o; o.x = vx; o.y = vy;
                *(float2*)&out[(size_t)r0 * HID + c] = o;
            }
            if (r1 < M) {
                float vx = acc.a[mt][nt][2] + bx, vy = acc.a[mt][nt][3] + by;
                if (add) {
                    float2 av = *(const float2*)&add[(size_t)r1 * HID + c];
                    vx += av.x; vy += av.y;
                }
                float2 o; o.x = vx; o.y = vy;
                *(float2*)&out[(size_t)r1 * HID + c] = o;
            }
        }
    }
}

// ==================== merged p1/p2 GEMM (A = fp32 h, split inline) ============
__global__ __launch_bounds__(256, 2) void mma_gemm2_kernel(
    const float* __restrict__ h,
    const bf16* __restrict__ Bhi0, const bf16* __restrict__ Blo0,
    float* __restrict__ out0, int M)
{
    extern __shared__ __align__(16) char sm[];
    uint32_t smem_base = smem_to_u32(sm);
    int tid = threadIdx.x, lane = tid & 31, wid = tid >> 5;
    int warp_m = wid & 1;
    int warp_n = wid >> 1;
    int sel = (blockIdx.x >= TILE_BLOCKS) ? 1 : 0;
    int m0 = (blockIdx.x - sel * TILE_BLOCKS) * 64;
    const bf16* Bhi = Bhi0 + (size_t)sel * HID * HID;
    const bf16* Blo = Blo0 + (size_t)sel * HID * HID;
    float* out = out0 + (size_t)sel * NN * HID;
    const int K = HID;

    AccT acc;
#pragma unroll
    for (int mt = 0; mt < 2; ++mt)
#pragma unroll
        for (int nt = 0; nt < 4; ++nt)
#pragma unroll
            for (int j = 0; j < 4; ++j) acc.a[mt][nt][j] = 0.f;

    auto load_B = [&](int stage, int k0) {
        uint32_t sbase = smem_base + stage * STAGE_BYTES + 2 * A_MAT_B;
#pragma unroll
        for (int it = 0; it < 8; ++it) {
            int idx = tid + it * 256;
            int bmat = idx >> 10;
            int rem = idx & 1023;
            int row = rem >> 3, seg = rem & 7;
            const bf16* src = (bmat ? Blo : Bhi) + (size_t)row * K + k0 + seg * 8;
            uint32_t dst = sbase + bmat * B_MAT_B + (uint32_t)(row * BKP + seg * 8) * 2;
            cp16(dst, src);
        }
    };

    auto load_A = [&](int stage, int k0) {
        uint32_t aHi = smem_base + stage * STAGE_BYTES;
        uint32_t aLo = aHi + A_MAT_B;
#pragma unroll
        for (int it = 0; it < 4; ++it) {
            int idx = tid + it * 256;
            int row = idx >> 4, s4 = idx & 15;
            float4 hv = *(const float4*)&h[(size_t)(m0 + row) * HID + k0 + s4 * 4];
            uint32_t hp0, lp0, hp1, lp1;
            split2(hv.x, hv.y, hp0, lp0);
            split2(hv.z, hv.w, hp1, lp1);
            uint32_t off = (uint32_t)(row * BKP + s4 * 4) * 2;
            asm volatile("st.shared.v2.b32 [%0], {%1,%2};" :: "r"(aHi + off), "r"(hp0), "r"(hp1));
            asm volatile("st.shared.v2.b32 [%0], {%1,%2};" :: "r"(aLo + off), "r"(lp0), "r"(lp1));
        }
    };

    load_B(0, 0);
    CP_COMMIT();
    load_A(0, 0);
    for (int c = 0; c < 2; ++c) {
        if (c == 0) {
            load_B(1, 64);
            CP_COMMIT();
            load_A(1, 64);
            CP_WAIT(1);
        } else {
            CP_WAIT(0);
        }
        __syncthreads();
        mma_chunk(smem_base + (c & 1) * STAGE_BYTES, lane, warp_m, warp_n, acc);
        __syncthreads();
    }
    epilogue(acc, m0, lane, warp_m, warp_n, nullptr, nullptr, out, M);
}

// ==================== FK GEMM fused: Fourier A in-kernel + edge conv + BN stats ====
// out aliases h. Edge aggregation for this CTA's 64 dst nodes happens after the
// MMA mainloop into a smem tile (reusing stage smem), epilogue adds from smem.
__global__ __launch_bounds__(256, 2) void fk_gemm_fused_kernel(
    const float* __restrict__ h,
    const bf16* __restrict__ Bhi, const bf16* __restrict__ Blo,
    const float* __restrict__ bias,
    const float* __restrict__ linw, const float* __restrict__ linb,
    const float* __restrict__ attw, const float* __restrict__ attb_p, int l,
    float* __restrict__ out, int M)
{
    extern __shared__ __align__(16) char sm[];
    uint32_t smem_base = smem_to_u32(sm);
    int tid = threadIdx.x, lane = tid & 31, wid = tid >> 5;
    int warp_m = wid & 1;
    int warp_n = wid >> 1;
    int m0 = blockIdx.x * 64;
    const int K = KFK;

    AccT acc;
#pragma unroll
    for (int mt = 0; mt < 2; ++mt)
#pragma unroll
        for (int nt = 0; nt < 4; ++nt)
#pragma unroll
            for (int j = 0; j < 4; ++j) acc.a[mt][nt][j] = 0.f;

    auto load_B = [&](int stage, int k0) {
        uint32_t sbase = smem_base + stage * STAGE_BYTES + 2 * A_MAT_B;
#pragma unroll
        for (int it = 0; it < 8; ++it) {
            int idx = tid + it * 256;
            int bmat = idx >> 10;
            int rem = idx & 1023;
            int row = rem >> 3, seg = rem & 7;
            const bf16* src = (bmat ? Blo : Bhi) + (size_t)row * K + k0 + seg * 8;
            uint32_t dst = sbase + bmat * B_MAT_B + (uint32_t)(row * BKP + seg * 8) * 2;
            cp16(dst, src);
        }
    };

    auto compute_A = [&](int stage, int c) {
        uint32_t aHi = smem_base + stage * STAGE_BYTES;
        uint32_t aLo = aHi + A_MAT_B;
        int i0 = c << 3;
#pragma unroll
        for (int half = 0; half < 2; ++half) {
            int p = tid + half * 256;
            int row = p >> 3, il = p & 7;
            float hv = h[(size_t)(m0 + row) * HID + i0 + il];
            float th = TWO_PI_F * hv;
            float s1, c1;
            __sincosf(th, &s1, &c1);
            float s = s1, cc = c1;
            uint32_t hi4[4], lo4[4];
#pragma unroll
            for (int fp = 0; fp < 4; ++fp) {
                float v0 = s + cc;
                float s2 = s * c1 + cc * s1;
                float c2 = cc * c1 - s * s1;
                s = s2; cc = c2;
                float v1 = s + cc;
                s2 = s * c1 + cc * s1;
                c2 = cc * c1 - s * s1;
                s = s2; cc = c2;
                split2(v0, v1, hi4[fp], lo4[fp]);
            }
            uint32_t off = (uint32_t)(row * BKP + il * 8) * 2;
            asm volatile("st.shared.v4.b32 [%0], {%1,%2,%3,%4};"
                :: "r"(aHi + off), "r"(hi4[0]), "r"(hi4[1]), "r"(hi4[2]), "r"(hi4[3]));
            asm volatile("st.shared.v4.b32 [%0], {%1,%2,%3,%4};"
                :: "r"(aLo + off), "r"(lo4[0]), "r"(lo4[1]), "r"(lo4[2]), "r"(lo4[3]));
        }
    };

    const int nchunks = K >> 6;   // 16
    compute_A(0, 0);
    load_B(0, 0);
    CP_COMMIT();

    for (int c = 0; c < nchunks; ++c) {
        if (c + 1 < nchunks) {
            load_B((c + 1) & 1, (c + 1) << 6);
            CP_COMMIT();
            compute_A((c + 1) & 1, c + 1);
            CP_WAIT(1);
        } else {
            CP_WAIT(0);
        }
        __syncthreads();
        mma_chunk(smem_base + (c & 1) * STAGE_BYTES, lane, warp_m, warp_n, acc);
        __syncthreads();
    }

    // ==== edge conv phase: aggregate into smem tile (reuse stage smem) ====
    float* tilef = (float*)sm;                       // 64 x 128 floats = 32 KB
    float* red = (float*)(sm + 64 * HID * 4);        // 256 floats for BN stats

    {
        float aw0 = attw[256], aw1 = attw[257], aw2 = attw[258];
        float ab = attb_p[l];
        int wwid = wid;                              // warp owns nodes wwid*8..+7
#pragma unroll 1
        for (int i = 0; i < 8; ++i) {
            int node = m0 + wwid * 8 + i;
            if (node >= NN) break;
            int start = g_rowstart[node], end = g_rowstart[node + 1];
            float q1d = g_q1[node];
            float a0 = 0.f, a1 = 0.f, a2 = 0.f, a3 = 0.f;
            float sa = 0.f, se0 = 0.f, se1 = 0.f, se2 = 0.f;
            int j = start;
            for (; j + 1 < end; j += 2) {
                int sA = g_esrc[j], sB = g_esrc[j + 1];
                float4 eA = g_eax[j], eB = g_eax[j + 1];
                float qA = g_q2[sA], qB = g_q2[sB];
                float4 vA = *(const float4*)&g_p12[(size_t)(NN + sA) * HID + lane * 4];
                float4 vB = *(const float4*)&g_p12[(size_t)(NN + sB) * HID + lane * 4];
                float lgA = q1d + qA + eA.x * aw0 + eA.y * aw1 + eA.z * aw2 + ab;
                float lgB = q1d + qB + eB.x * aw0 + eB.y * aw1 + eB.z * aw2 + ab;
                float alA = 1.f / (1.f + __expf(-lgA));
                float alB = 1.f / (1.f + __expf(-lgB));
                a0 += alA * vA.x + alB * vB.x;
                a1 += alA * vA.y + alB * vB.y;
                a2 += alA * vA.z + alB * vB.z;
                a3 += alA * vA.w + alB * vB.w;
                sa += alA + alB;
                se0 += alA * eA.x + alB * eB.x;
                se1 += alA * eA.y + alB * eB.y;
                se2 += alA * eA.z + alB * eB.z;
            }
            if (j < end) {
                int src = g_esrc[j];
                float4 e4 = g_eax[j];
                float lg = q1d + g_q2[src] + e4.x * aw0 + e4.y * aw1 + e4.z * aw2 + ab;
                float al = 1.f / (1.f + __expf(-lg));
                float4 v2 = *(const float4*)&g_p12[(size_t)(NN + src) * HID + lane * 4];
                a0 += al * v2.x; a1 += al * v2.y; a2 += al * v2.z; a3 += al * v2.w;
                sa += al; se0 += al * e4.x; se1 += al * e4.y; se2 += al * e4.z;
            }
            int c = lane * 4;
            float4 w0v = *(const float4*)&linw[256 * HID + c];
            float4 w1v = *(const float4*)&linw[257 * HID + c];
            float4 w2v = *(const float4*)&linw[258 * HID + c];
            float4 lbv = *(const float4*)&linb[c];
            float4 p1v = *(const float4*)&g_p12[(size_t)node * HID + c];
            float4 r;
            r.x = a0 + se0 * w0v.x + se1 * w1v.x + se2 * w2v.x + sa * (p1v.x + lbv.x);
            r.y = a1 + se0 * w0v.y + se1 * w1v.y + se2 * w2v.y + sa * (p1v.y + lbv.y);
            r.z = a2 + se0 * w0v.z + se1 * w1v.z + se2 * w2v.z + sa * (p1v.z + lbv.z);
            r.w = a3 + se0 * w0v.w + se1 * w1v.w + se2 * w2v.w + sa * (p1v.w + lbv.w);
            *(float4*)&tilef[(wwid * 8 + i) * HID + c] = r;
        }
    }

    // zero BN reduction buffer
    if (tid < 256) red[tid] = 0.f;
    __syncthreads();

    // ==== epilogue: h = acc + bias + edge_tile; accumulate BN stats ====
    float colsum[8], colssq[8];
#pragma unroll
    for (int q = 0; q < 8; ++q) { colsum[q] = 0.f; colssq[q] = 0.f; }

#pragma unroll
    for (int mt = 0; mt < 2; ++mt) {
        int lr0 = warp_m * 32 + mt * 16 + (lane >> 2);
        int lr1 = lr0 + 8;
        int r0 = m0 + lr0;
        int r1 = m0 + lr1;
#pragma unroll
        for (int nt = 0; nt < 4; ++nt) {
            int c = warp_n * 32 + nt * 8 + 2 * (lane & 3);
            float2 bv = *(const float2*)&bias[c];
            if (r0 < M) {
                float2 av = *(const float2*)&tilef[lr0 * HID + c];
                float vx = acc.a[mt][nt][0] + bv.x + av.x;
                float vy = acc.a[mt][nt][1] + bv.y + av.y;
                float2 o; o.x = vx; o.y = vy;
                *(float2*)&out[(size_t)r0 * HID + c] = o;
                colsum[nt * 2] += vx; colssq[nt * 2] += vx * vx;
                colsum[nt * 2 + 1] += vy; colssq[nt * 2 + 1] += vy * vy;
            }
            if (r1 < M) {
                float2 av = *(const float2*)&tilef[lr1 * HID + c];
                float vx = acc.a[mt][nt][2] + bv.x + av.x;
                float vy = acc.a[mt][nt][3] + bv.y + av.y;
                float2 o; o.x = vx; o.y = vy;
                *(float2*)&out[(size_t)r1 * HID + c] = o;
                colsum[nt * 2] += vx; colssq[nt * 2] += vx * vx;
                colsum[nt * 2 + 1] += vy; colssq[nt * 2 + 1] += vy * vy;
            }
        }
    }
#pragma unroll
    for (int nt = 0; nt < 4; ++nt) {
#pragma unroll
        for (int k = 0; k < 2; ++k) {
            int c = warp_n * 32 + nt * 8 + 2 * (lane & 3) + k;
            atomicAdd(&red[c], colsum[nt * 2 + k]);
            atomicAdd(&red[128 + c], colssq[nt * 2 + k]);
        }
    }
    __syncthreads();
    if (tid < 256) atomicAdd(&g_stats[tid], red[tid]);
}

// ==================== CSR construction ====================
__global__ void hist_kernel(const int* __restrict__ ei) {
    int e = blockIdx.x * blockDim.x + threadIdx.x;
    if (e < NE) atomicAdd(&g_count[ei[NE + e]], 1);
}

#define SCH 20
__global__ __launch_bounds__(1024) void scan_kernel() {
    int t = threadIdx.x;
    int base = t * SCH;
    int loc[SCH];
    int s = 0;
#pragma unroll
    for (int i = 0; i < SCH; ++i) {
        int n = base + i;
        int v = (n < NN) ? g_count[n] : 0;
        loc[i] = s;
        s += v;
    }
    int lane = t & 31, w = t >> 5;
    int ps = s;
#pragma unroll
    for (int o = 1; o < 32; o <<= 1) {
        int x = __shfl_up_sync(0xffffffffu, ps, o);
        if (lane >= o) ps += x;
    }
    __shared__ int wsum[32];
    if (lane == 31) wsum[w] = ps;
    __syncthreads();
    if (w == 0) {
        int x = wsum[lane];
#pragma unroll
        for (int o = 1; o < 32; o <<= 1) {
            int y = __shfl_up_sync(0xffffffffu, x, o);
            if (lane >= o) x += y;
        }
        wsum[lane] = x;
    }
    __syncthreads();
    int off = ps - s + (w > 0 ? wsum[w - 1] : 0);
#pragma unroll
    for (int i = 0; i < SCH; ++i) {
        int n = base + i;
        if (n < NN) g_rowstart[n] = off + loc[i];
    }
    if (t == 0) g_rowstart[NN] = NE;
}

__global__ void scatter_kernel(const int* __restrict__ ei) {
    int e = blockIdx.x * blockDim.x + threadIdx.x;
    if (e < NE) {
        int dst = ei[NE + e];
        int pos = g_rowstart[dst] + atomicAdd(&g_count[dst], 1);
        g_perm[pos] = e;
    }
}

__global__ void csr_gather_kernel(const int* __restrict__ ei, const float* __restrict__ ea) {
    int j = blockIdx.x * blockDim.x + threadIdx.x;
    if (j < NE) {
        int e = g_perm[j];
        g_esrc[j] = ei[e];
        float4 v;
        v.x = ea[3 * e + 0]; v.y = ea[3 * e + 1]; v.z = ea[3 * e + 2]; v.w = 0.f;
        g_eax[j] = v;
    }
}

// ==================== init / embed ====================
__global__ void pool_init_kernel() {
    int i = blockIdx.x * blockDim.x + threadIdx.x;
    int stride = gridDim.x * blockDim.x;
    for (int j = i; j < NB * HID; j += stride) g_pooled[j] = 0.f;
    if (i == 0) { g_umax = 0u; g_sumexp = 0.f; }
}

__global__ __launch_bounds__(256) void node_embed_q_kernel(
    const float* __restrict__ x, const float* __restrict__ w,
    const float* __restrict__ b, const float* __restrict__ attw) {
    int row = (blockIdx.x * blockDim.x + threadIdx.x) >> 5;
    int lane = threadIdx.x & 31;
    if (row >= NN) return;
    int c = lane * 4;
    float4 xv = *(const float4*)&x[row * 4];
    float v[4];
#pragma unroll
    for (int jj = 0; jj < 4; ++jj) {
        int cc = c + jj;
        v[jj] = b[cc] + xv.x * w[cc] + xv.y * w[HID + cc]
              + xv.z * w[2 * HID + cc] + xv.w * w[3 * HID + cc];
    }
    size_t o = (size_t)row * HID + c;
    *(float4*)&g_h[o] = make_float4(v[0], v[1], v[2], v[3]);
    float s1 = v[0] * attw[c] + v[1] * attw[c + 1] + v[2] * attw[c + 2] + v[3] * attw[c + 3];
    float s2 = v[0] * attw[HID + c] + v[1] * attw[HID + c + 1]
             + v[2] * attw[HID + c + 2] + v[3] * attw[HID + c + 3];
#pragma unroll
    for (int o2 = 16; o2 > 0; o2 >>= 1) {
        s1 += __shfl_xor_sync(0xffffffffu, s1, o2);
        s2 += __shfl_xor_sync(0xffffffffu, s2, o2);
    }
    if (lane == 0) { g_q1[row] = s1; g_q2[row] = s2; }
}

// ==================== weight conversions ====================
__global__ void conv_fkw_kernel(const float* __restrict__ fkw) {
    int idx = blockIdx.x * blockDim.x + threadIdx.x;
    if (idx >= DEPTH * HID * HID) return;
    int l = idx >> 14;
    int rem = idx & 16383;
    int n = rem >> 7, i = rem & 127;
    uint32_t hi4[4], lo4[4];
#pragma unroll
    for (int fp = 0; fp < 4; ++fp) {
        float w0 = fkw[(((size_t)l * NFREQ + 2 * fp) * HID + i) * HID + n];
        float w1 = fkw[(((size_t)l * NFREQ + 2 * fp + 1) * HID + i) * HID + n];
        split2(w0, w1, hi4[fp], lo4[fp]);
    }
    size_t o = ((size_t)l * HID + n) * KFK + i * 8;
    *(uint4*)&g_Wfk_hi[o] = make_uint4(hi4[0], hi4[1], hi4[2], hi4[3]);
    *(uint4*)&g_Wfk_lo[o] = make_uint4(lo4[0], lo4[1], lo4[2], lo4[3]);
}

__global__ void conv_linw_kernel(const float* __restrict__ linw) {
    int idx = blockIdx.x * blockDim.x + threadIdx.x;
    if (idx >= DEPTH * 2 * HID * HID) return;
    int l = idx / (2 * HID * HID);
    int rem = idx - l * (2 * HID * HID);
    int p = rem >> 14;
    int nk = rem & 16383;
    int n = nk >> 7, k = nk & 127;
    float w = linw[((size_t)l * 259 + p * 128 + k) * HID + n];
    bf16 hi = __float2bfloat16(w);
    bf16 lo = __float2bfloat16(w - __bfloat162float(hi));
    size_t o = (((size_t)l * 2 + p) * HID + n) * HID + k;
    g_Wlin_hi[o] = hi;
    g_Wlin_lo[o] = lo;
}

// ==================== BN apply + q / pool-logit (warp per row) ====================
__device__ __forceinline__ unsigned float_key(float f) {
    unsigned u = __float_as_uint(f);
    return (u & 0x80000000u) ? ~u : (u | 0x80000000u);
}

__global__ __launch_bounds__(256) void bn_apply_q_kernel(
    float* __restrict__ h, const float* __restrict__ g, const float* __restrict__ b,
    const float* __restrict__ wa, const float* __restrict__ wb,
    const float* __restrict__ pb) {
    int row = (blockIdx.x * blockDim.x + threadIdx.x) >> 5;
    int lane = threadIdx.x & 31;
    if (row >= NN) return;
    int c = lane * 4;
    size_t o = (size_t)row * HID + c;
    float4 hv = *(const float4*)&h[o];
    float v[4] = { hv.x, hv.y, hv.z, hv.w };
    const float invN = 1.f / (float)NN;
#pragma unroll
    for (int jj = 0; jj < 4; ++jj) {
        int cc = c + jj;
        float mu = g_stats[cc] * invN;
        float var = g_stats[HID + cc] * invN - mu * mu;
        float rstd = rsqrtf(var + 1e-5f);
        v[jj] = fmaxf((v[jj] - mu) * rstd * g[cc] + b[cc], 0.f);
    }
    *(float4*)&h[o] = make_float4(v[0], v[1], v[2], v[3]);

    float s1 = v[0] * wa[c] + v[1] * wa[c + 1] + v[2] * wa[c + 2] + v[3] * wa[c + 3];
    if (wb) {
        float s2 = v[0] * wb[c] + v[1] * wb[c + 1] + v[2] * wb[c + 2] + v[3] * wb[c + 3];
#pragma unroll
        for (int o2 = 16; o2 > 0; o2 >>= 1) {
            s1 += __shfl_xor_sync(0xffffffffu, s1, o2);
            s2 += __shfl_xor_sync(0xffffffffu, s2, o2);
        }
        if (lane == 0) { g_q1[row] = s1; g_q2[row] = s2; }
    } else {
#pragma unroll
        for (int o2 = 16; o2 > 0; o2 >>= 1)
            s1 += __shfl_xor_sync(0xffffffffu, s1, o2);
        if (lane == 0) {
            s1 += pb[0];
            g_logits[row] = s1;
            atomicMax(&g_umax, float_key(s1));
        }
    }
}

// ==================== attention pooling tail ====================
__global__ void pool_sumexp_kernel() {
    unsigned k = g_umax;
    float maxv = (k & 0x80000000u) ? __uint_as_float(k ^ 0x80000000u)
                                   : __uint_as_float(~k);
    int i = blockIdx.x * blockDim.x + threadIdx.x;
    int stride = gridDim.x * blockDim.x;
    float local = 0.f;
    for (; i < NN; i += stride) local += __expf(g_logits[i] - maxv);
#pragma unroll
    for (int o = 16; o > 0; o >>= 1) local += __shfl_xor_sync(0xffffffffu, local, o);
    __shared__ float ws[8];
    int lane = threadIdx.x & 31, wid = threadIdx.x >> 5;
    if (lane == 0) ws[wid] = local;
    __syncthreads();
    if (wid == 0) {
        float v = (lane < (blockDim.x >> 5)) ? ws[lane] : 0.f;
#pragma unroll
        for (int o = 16; o > 0; o >>= 1) v += __shfl_xor_sync(0xffffffffu, v, o);
        if (lane == 0) atomicAdd(&g_sumexp, v);
    }
}

__global__ void pool_scatter_kernel(const float* __restrict__ h,
                                    const int* __restrict__ batch) {
    int gwarp = (blockIdx.x * blockDim.x + threadIdx.x) >> 5;
    int lane = threadIdx.x & 31;
    if (gwarp >= NN) return;
    unsigned k = g_umax;
    float maxv = (k & 0x80000000u) ? __uint_as_float(k ^ 0x80000000u)
                                   : __uint_as_float(~k);
    float w = __expf(g_logits[gwarp] - maxv) / g_sumexp;
    int b = batch[gwarp];
    int c = lane * 4;
    float4 hv = *(const float4*)&h[(size_t)gwarp * HID + c];
    float* outp = &g_pooled[b * HID + c];
    atomicAdd(outp + 0, w * hv.x);
    atomicAdd(outp + 1, w * hv.y);
    atomicAdd(outp + 2, w * hv.z);
    atomicAdd(outp + 3, w * hv.w);
}

// ==================== heads ====================
__global__ __launch_bounds__(128) void head_kernel(
    const float* __restrict__ sg_table, const int* __restrict__ sgidx,
    const float* __restrict__ hw1, const float* __restrict__ hb1,
    const float* __restrict__ w2e, const float* __restrict__ b2e,
    const float* __restrict__ w2s, const float* __restrict__ b2s,
    const float* __restrict__ w2c, const float* __restrict__ b2c,
    const float* __restrict__ w2m, const float* __restrict__ b2m,
    float* __restrict__ out)
{
    int b = blockIdx.x;
    int t = threadIdx.x;
    __shared__ float comb[2 * HID];
    __shared__ float z[HID];
    comb[t] = g_pooled[b * HID + t];
    comb[HID + t] = sg_table[sgidx[b] * HID + t];
    __syncthreads();

    const float* w2arr[4] = { w2e, w2s, w2c, w2m };
    const float* b2arr[4] = { b2e, b2s, b2c, b2m };
    const int od[4] = { 1, 3, 7, 3 };
    const int off[4] = { 0, NB * 1, NB * 4, NB * 11 };

    for (int i = 0; i < 4; ++i) {
        float accz = hb1[i * HID + t];
        const float* W = hw1 + (size_t)i * 2 * HID * HID;
#pragma unroll 8
        for (int j = 0; j < 2 * HID; ++j) accz += comb[j] * W[j * HID + t];
        z[t] = fmaxf(accz, 0.f);
        __syncthreads();
        if (t < od[i]) {
            const float* w2 = w2arr[i];
            float acc = b2arr[i][t];
            for (int j = 0; j < HID; ++j) acc += z[j] * w2[j * od[i] + t];
            out[off[i] + b * od[i] + t] = acc;
        }
        __syncthreads();
    }
}

// ==================== host ====================
extern "C" void kernel_launch(void* const* d_in, const int* in_sizes, int n_in,
                              void* d_out, int out_size) {
    const float* x        = (const float*)d_in[0];
    const int*   ei       = (const int*)d_in[1];
    const float* ea       = (const float*)d_in[2];
    const int*   batch    = (const int*)d_in[3];
    const int*   sgidx    = (const int*)d_in[4];
    const float* node_w   = (const float*)d_in[5];
    const float* node_b   = (const float*)d_in[6];
    const float* sg_table = (const float*)d_in[7];
    const float* lin_w    = (const float*)d_in[8];
    const float* lin_b    = (const float*)d_in[9];
    const float* att_w    = (const float*)d_in[10];
    const float* att_b    = (const float*)d_in[11];
    const float* fk_w     = (const float*)d_in[12];
    const float* fk_b     = (const float*)d_in[13];
    const float* bn_g     = (const float*)d_in[14];
    const float* bn_b     = (const float*)d_in[15];
    const float* pool_w   = (const float*)d_in[16];
    const float* pool_b   = (const float*)d_in[17];
    const float* head_w1  = (const float*)d_in[18];
    const float* head_b1  = (const float*)d_in[19];
    const float* w2e = (const float*)d_in[20];
    const float* b2e = (const float*)d_in[21];
    const float* w2s = (const float*)d_in[22];
    const float* b2s = (const float*)d_in[23];
    const float* w2c = (const float*)d_in[24];
    const float* b2c = (const float*)d_in[25];
    const float* w2m = (const float*)d_in[26];
    const float* b2m = (const float*)d_in[27];
    float* out = (float*)d_out;

    cudaFuncSetAttribute(mma_gemm2_kernel, cudaFuncAttributeMaxDynamicSharedMemorySize,
                         GEMM_SMEM);
    cudaFuncSetAttribute(fk_gemm_fused_kernel, cudaFuncAttributeMaxDynamicSharedMemorySize,
                         GEMM_SMEM);

    float *p_h, *p_stats, *p_p12;
    bf16 *p_Wfk_hi, *p_Wfk_lo, *p_Wlin_hi, *p_Wlin_lo;
    int *p_count;
    cudaGetSymbolAddress((void**)&p_h, g_h);
    cudaGetSymbolAddress((void**)&p_stats, g_stats);
    cudaGetSymbolAddress((void**)&p_Wfk_hi, g_Wfk_hi);
    cudaGetSymbolAddress((void**)&p_Wfk_lo, g_Wfk_lo);
    cudaGetSymbolAddress((void**)&p_Wlin_hi, g_Wlin_hi);
    cudaGetSymbolAddress((void**)&p_Wlin_lo, g_Wlin_lo);
    cudaGetSymbolAddress((void**)&p_count, g_count);
    cudaGetSymbolAddress((void**)&p_p12, g_p12);

    const int warp_blocks = (NN + 7) / 8;             // 2500

    // CSR construction + payload gather (edge_index is layer-invariant)
    cudaMemsetAsync(p_count, 0, NN * sizeof(int), 0);
    hist_kernel<<<(NE + 255) / 256, 256>>>(ei);
    scan_kernel<<<1, 1024>>>();
    cudaMemsetAsync(p_count, 0, NN * sizeof(int), 0);
    scatter_kernel<<<(NE + 255) / 256, 256>>>(ei);
    csr_gather_kernel<<<(NE + 255) / 256, 256>>>(ei, ea);

    conv_fkw_kernel<<<(DEPTH * HID * HID + 255) / 256, 256>>>(fk_w);
    conv_linw_kernel<<<(DEPTH * 2 * HID * HID + 255) / 256, 256>>>(lin_w);

    pool_init_kernel<<<32, 256>>>();
    node_embed_q_kernel<<<warp_blocks, 256>>>(x, node_w, node_b, att_w);

    for (int l = 0; l < DEPTH; ++l) {
        const float* lw = lin_w + (size_t)l * 259 * HID;
        const float* lb = lin_b + (size_t)l * HID;
        const float* aw = att_w + (size_t)l * 259;
        const bf16* Wlin_hi = p_Wlin_hi + (size_t)l * 2 * HID * HID;
        const bf16* Wlin_lo = p_Wlin_lo + (size_t)l * 2 * HID * HID;

        mma_gemm2_kernel<<<2 * TILE_BLOCKS, 256, GEMM_SMEM>>>(
            p_h, Wlin_hi, Wlin_lo, p_p12, NN);
        cudaMemsetAsync(p_stats, 0, 2 * HID * sizeof(float), 0);
        fk_gemm_fused_kernel<<<TILE_BLOCKS, 256, GEMM_SMEM>>>(
            p_h, p_Wfk_hi + (size_t)l * HID * KFK, p_Wfk_lo + (size_t)l * HID * KFK,
            fk_b + (size_t)l * HID, lw, lb, aw, att_b, l, p_h, NN);
        if (l < DEPTH - 1) {
            const float* awn = att_w + (size_t)(l + 1) * 259;
            bn_apply_q_kernel<<<warp_blocks, 256>>>(
                p_h, bn_g + (size_t)l * HID, bn_b + (size_t)l * HID,
                awn, awn + HID, nullptr);
        } else {
            bn_apply_q_kernel<<<warp_blocks, 256>>>(
                p_h, bn_g + (size_t)l * HID, bn_b + (size_t)l * HID,
                pool_w, nullptr, pool_b);
        }
    }

    pool_sumexp_kernel<<<80, 256>>>();
    pool_scatter_kernel<<<warp_blocks, 256>>>(p_h, batch);

    head_kernel<<<NB, 128>>>(sg_table, sgidx, head_w1, head_b1,
                             w2e, b2e, w2s, b2s, w2c, b2c, w2m, b2m, out);
}